// round 14
// baseline (speedup 1.0000x reference)
#include <cuda_runtime.h>
#include <cuda_fp16.h>
#include <cstdint>

// ============================================================================
// CellLSTM on GB300 (sm_103a)
//   z = [x|h] @ [Wi|Wf|Wg|Wo] + b ; gates; c' = f*c + i*g ; h' = o*tanh(c')
//   R14: TS-mode MMA (A in TMEM, B in SMEM). R12/R13 measured a constant
//   202cyc per K=16 dispatch vs 128 floor, invariant to ring depth/signaling:
//   SS-mode operand fetch (12KB/dispatch @ ~64B/cyc) is the wall. TS mode
//   fetches only B (8KB -> 128cyc = floor); A flows LDG->regs->tcgen05.st
//   (STTM 256B/cyc) via the otherwise-idle consumer warps 1-3 + warp 0.
// ============================================================================

#if defined(__CUDA_ARCH_FEAT_SM103_ALL) || defined(__CUDA_ARCH_FEAT_SM100_ALL)
#define USE_TCGEN05 1
#else
#define USE_TCGEN05 0
#endif

#define B_DIM 8192
#define T_DIM 1024
#define U_DIM 1024
#define K_DIM 2048
#define N_DIM 4096

#define BM 128
#define BN 256
#define BK 64
#define KTILES (K_DIM / BK)         // 32 k-iterations per tile
#define NTILES_TOTAL ((B_DIM / BM) * (N_DIM / BN))   // 64*16 = 1024
#define NTILES_N (N_DIM / BN)       // 16
#define GRID_X 128                  // 1024 tiles / 128 = exactly 8 per CTA
#define MAX_TILES_PER_CTA 8
#define GEMM_THREADS 256

// ---------------- scratch (device globals: allocation-rule-safe) -----------
__device__ __align__(16) __half g_A_h[(size_t)B_DIM * K_DIM];
// W transposed & gate-interleaved: row n = u*4 + gate, K-major
__device__ __align__(16) __half g_W_h[(size_t)N_DIM * K_DIM];

// ---------------- arch-neutral helpers -------------------------------------
__device__ __forceinline__ uint32_t smem_u32(const void* p) {
    uint32_t a;
    asm("{ .reg .u64 t; cvta.to.shared.u64 t, %1; cvt.u32.u64 %0, t; }"
        : "=r"(a) : "l"(p));
    return a;
}

#define SWZ128(off) ((off) ^ (((off) >> 3) & 0x70))

__device__ __forceinline__ float tanh_fast(float x) {
    float y;
    asm("tanh.approx.f32 %0, %1;" : "=f"(y) : "f"(x));
    return y;
}

// sigmoid(z) = 0.5*tanh(z/2) + 0.5
__device__ __forceinline__ float fast_sigmoid(float z) {
    return fmaf(0.5f, tanh_fast(0.5f * z), 0.5f);
}

#if USE_TCGEN05
// ---------------- tcgen05 / mbarrier / cp.async helpers --------------------
__device__ __forceinline__ uint32_t elect_one() {
    uint32_t pred;
    asm volatile(
        "{\n\t.reg .pred p;\n\telect.sync _|p, 0xFFFFFFFF;\n\t"
        "selp.b32 %0, 1, 0, p;\n\t}" : "=r"(pred));
    return pred;
}

#define MBARRIER_INIT(addr, cnt) \
    asm volatile("mbarrier.init.shared.b64 [%0], %1;" \
                 :: "r"((uint32_t)(addr)), "r"((uint32_t)(cnt)) : "memory")

#define MBARRIER_INVAL(addr) \
    asm volatile("mbarrier.inval.shared.b64 [%0];" \
                 :: "r"((uint32_t)(addr)) : "memory")

#define CP_ASYNC_MBAR_ARRIVE(addr) \
    asm volatile("cp.async.mbarrier.arrive.noinc.shared::cta.b64 [%0];" \
                 :: "r"((uint32_t)(addr)) : "memory")

#define MBARRIER_WAIT_PARITY(mbar_smem_addr, phase_parity) do { \
    uint32_t _mbar = (uint32_t)(mbar_smem_addr); \
    uint32_t _parity = (uint32_t)(phase_parity); \
    uint32_t _done; \
    asm volatile( \
        "{\n\t.reg .pred p;\n\t" \
        "mbarrier.try_wait.parity.acquire.cta.shared::cta.b64 p, [%1], %2;\n\t" \
        "selp.b32 %0, 1, 0, p;\n\t}" \
        : "=r"(_done) : "r"(_mbar), "r"(_parity) : "memory"); \
    if (!_done) { \
        asm volatile( \
            "{\n\t.reg .pred P1;\n\t" \
            "WAIT_LOOP_%=:\n\t" \
            "mbarrier.try_wait.parity.acquire.cta.shared::cta.b64 P1, [%0], %1, 0x989680;\n\t" \
            "@P1 bra.uni WAIT_DONE_%=;\n\t" \
            "bra.uni WAIT_LOOP_%=;\n\t" \
            "WAIT_DONE_%=:\n\t}" \
            :: "r"(_mbar), "r"(_parity) : "memory"); \
    } \
} while (0)

#define NAMED_BARRIER_SYNC(id, cnt) \
    asm volatile("bar.sync %0, %1;" :: "r"(id), "r"(cnt) : "memory")

#define TCGEN05_ALLOC(smem_result_addr, nCols) \
    asm volatile("tcgen05.alloc.cta_group::1.sync.aligned.shared::cta.b32 [%0], %1;" \
                 :: "r"((uint32_t)(smem_result_addr)), "r"((uint32_t)(nCols)) : "memory")

#define TCGEN05_DEALLOC(tmem_addr, nCols) \
    asm volatile("tcgen05.dealloc.cta_group::1.sync.aligned.b32 %0, %1;" \
                 :: "r"(tmem_addr), "r"((uint32_t)(nCols)))

#define TCGEN05_COMMIT(mbar_smem_addr) \
    asm volatile("tcgen05.commit.cta_group::1.mbarrier::arrive::one.shared::cluster.b64 [%0];" \
                 :: "r"((uint32_t)(mbar_smem_addr)) : "memory")

#define TCGEN05_FENCE_AFTER() \
    asm volatile("tcgen05.fence::after_thread_sync;" ::: "memory")
#define TCGEN05_FENCE_BEFORE() \
    asm volatile("tcgen05.fence::before_thread_sync;" ::: "memory")
#define TCGEN05_WAIT_LD() \
    asm volatile("tcgen05.wait::ld.sync.aligned;" ::: "memory")
#define TCGEN05_WAIT_ST() \
    asm volatile("tcgen05.wait::st.sync.aligned;" ::: "memory")

#define FENCE_PROXY_ASYNC() \
    asm volatile("fence.proxy.async.shared::cta;" ::: "memory")

__device__ __forceinline__ void cp16(uint32_t dst, const void* src) {
    asm volatile("cp.async.cg.shared.global [%0], [%1], 16;"
                 :: "r"(dst), "l"(src) : "memory");
}

#define TCGEN05_LD_32X32B_X32(r, tmem_addr) \
    asm volatile( \
        "tcgen05.ld.sync.aligned.32x32b.x32.b32 " \
        "{%0, %1, %2, %3, %4, %5, %6, %7, " \
        " %8, %9, %10, %11, %12, %13, %14, %15, " \
        " %16, %17, %18, %19, %20, %21, %22, %23, " \
        " %24, %25, %26, %27, %28, %29, %30, %31}, [%32];" \
        : "=r"((r)[0]),  "=r"((r)[1]),  "=r"((r)[2]),  "=r"((r)[3]), \
          "=r"((r)[4]),  "=r"((r)[5]),  "=r"((r)[6]),  "=r"((r)[7]), \
          "=r"((r)[8]),  "=r"((r)[9]),  "=r"((r)[10]), "=r"((r)[11]), \
          "=r"((r)[12]), "=r"((r)[13]), "=r"((r)[14]), "=r"((r)[15]), \
          "=r"((r)[16]), "=r"((r)[17]), "=r"((r)[18]), "=r"((r)[19]), \
          "=r"((r)[20]), "=r"((r)[21]), "=r"((r)[22]), "=r"((r)[23]), \
          "=r"((r)[24]), "=r"((r)[25]), "=r"((r)[26]), "=r"((r)[27]), \
          "=r"((r)[28]), "=r"((r)[29]), "=r"((r)[30]), "=r"((r)[31]) \
        : "r"(tmem_addr))

#define TCGEN05_ST_32X32B_X32(tmem_addr, r) \
    asm volatile( \
        "tcgen05.st.sync.aligned.32x32b.x32.b32 [%0], " \
        "{%1, %2, %3, %4, %5, %6, %7, %8, " \
        " %9, %10, %11, %12, %13, %14, %15, %16, " \
        " %17, %18, %19, %20, %21, %22, %23, %24, " \
        " %25, %26, %27, %28, %29, %30, %31, %32};" \
        :: "r"(tmem_addr), \
           "r"((r)[0]),  "r"((r)[1]),  "r"((r)[2]),  "r"((r)[3]), \
           "r"((r)[4]),  "r"((r)[5]),  "r"((r)[6]),  "r"((r)[7]), \
           "r"((r)[8]),  "r"((r)[9]),  "r"((r)[10]), "r"((r)[11]), \
           "r"((r)[12]), "r"((r)[13]), "r"((r)[14]), "r"((r)[15]), \
           "r"((r)[16]), "r"((r)[17]), "r"((r)[18]), "r"((r)[19]), \
           "r"((r)[20]), "r"((r)[21]), "r"((r)[22]), "r"((r)[23]), \
           "r"((r)[24]), "r"((r)[25]), "r"((r)[26]), "r"((r)[27]), \
           "r"((r)[28]), "r"((r)[29]), "r"((r)[30]), "r"((r)[31]) \
        : "memory")

// K-major SW128 smem descriptor (verified: test_mma_iter)
static constexpr uint64_t SMEM_DESC_BASE_SW128 =
    (uint64_t(2)  << 61) | (uint64_t(1) << 46) |
    (uint64_t(64) << 32) | (uint64_t(1) << 16);

__device__ __forceinline__ uint64_t make_desc(uint32_t addr) {
    return SMEM_DESC_BASE_SW128 | ((uint64_t)(addr >> 4) & 0x3FFF);
}

// idesc kind::f16, FP16 inputs, f32 accum, M=128, N=256
static constexpr uint32_t MMA_IDESC =
    (1u << 4) | (0u << 7) | (0u << 10) | ((BN / 8) << 17) | ((BM / 16) << 24);

// TS form: A in TMEM (verified pattern: test_mma.cu / test_mma_iter.cu)
__device__ __forceinline__ void mma_f16_ts(uint32_t d, uint32_t a_tmem,
                                           uint64_t bd, uint32_t idesc,
                                           uint32_t acc) {
    asm volatile(
        "{\n\t.reg .pred p;\n\t"
        "setp.ne.u32 p, %4, 0;\n\t"
        "tcgen05.mma.cta_group::1.kind::f16 [%0], [%1], %2, %3, {%5, %5, %5, %5}, p;\n\t"
        "}"
        :: "r"(d), "r"(a_tmem), "l"(bd), "r"(idesc), "r"(acc), "r"(0u)
        : "memory");
}
#endif // USE_TCGEN05

// ---------------- fused prep kernel -----------------------------------------
#define PREP_A_BLOCKS ((int)(((size_t)B_DIM * K_DIM / 8) / 256))   // 8192
#define PREP_W_BLOCKS ((K_DIM / 32) * (U_DIM / 32) * 4)            // 8192

__global__ void prep_fused_kernel(const float* __restrict__ x,
                                  const float* __restrict__ h,
                                  const float* __restrict__ Wi,
                                  const float* __restrict__ Wf,
                                  const float* __restrict__ Wg,
                                  const float* __restrict__ Wo) {
    __shared__ float tile[32][33];
    int bid = blockIdx.x;
    int tid = threadIdx.x;

    if (bid < PREP_A_BLOCKS) {
        size_t idx8 = ((size_t)bid * 256 + tid) * 8;
        int m = (int)(idx8 / K_DIM);
        int k = (int)(idx8 % K_DIM);
        const float* src = (k < T_DIM) ? (x + (size_t)m * T_DIM + k)
                                       : (h + (size_t)m * U_DIM + (k - T_DIM));
        float4 v0 = *reinterpret_cast<const float4*>(src);
        float4 v1 = *reinterpret_cast<const float4*>(src + 4);

        union Pack { __half b[8]; uint4 u; } p;
        p.b[0] = __float2half_rn(v0.x); p.b[1] = __float2half_rn(v0.y);
        p.b[2] = __float2half_rn(v0.z); p.b[3] = __float2half_rn(v0.w);
        p.b[4] = __float2half_rn(v1.x); p.b[5] = __float2half_rn(v1.y);
        p.b[6] = __float2half_rn(v1.z); p.b[7] = __float2half_rn(v1.w);
        *reinterpret_cast<uint4*>(g_A_h + idx8) = p.u;
    } else {
        int w = bid - PREP_A_BLOCKS;               // 0..8191
        int gate = w >> 11;
        int rem = w & 2047;
        int k0 = (rem & 63) * 32;
        int u0 = (rem >> 6) * 32;
        const float* W = (gate == 0) ? Wi : (gate == 1) ? Wf
                        : (gate == 2) ? Wg : Wo;
        int tx = tid & 31;
        int ty = tid >> 5;

#pragma unroll
        for (int i = 0; i < 4; i++) {
            int k = k0 + ty + i * 8;
            tile[ty + i * 8][tx] = W[(size_t)k * U_DIM + u0 + tx];
        }
        __syncthreads();
#pragma unroll
        for (int i = 0; i < 4; i++) {
            int u = u0 + ty + i * 8;
            float v = tile[tx][ty + i * 8];        // = W[k0+tx, u]
            size_t off = (size_t)(u * 4 + gate) * K_DIM + k0 + tx;
            g_W_h[off] = __float2half_rn(v);
        }
    }
}

// ---------------- GEMM + LSTM epilogue -------------------------------------
// SMEM map:
//   [0]      tmem ptr
//   [8]      fullB[4] mbarriers  -- cp.async.mbarrier.arrive (B data landed)
//   [64]     mma[4]   mbarriers  -- MMA commit frees B slot + A TMEM slot
//   [1024]   4 stages x B(32KB) = 128KB ring (SW128, 256 rows x 128B)
// TMEM map: D = cols 0..255 (fp32), A ring = 4 slots x 32 cols at 256..383
#define SM_TMEM 0
#define SM_FULL 8
#define SM_MMAB 64
#define SM_STAGE 1024
#define B_TILE_BYTES 32768                  // 256 rows x 128B
#define STAGE_BYTES B_TILE_BYTES
#define NSTAGES 4
#define GEMM_SMEM (SM_STAGE + NSTAGES * STAGE_BYTES)        // 132096
#define TMEM_A_OFF 256
#define N_PRODUCER_THREADS 128

#if USE_TCGEN05
// Each of the 128 producer threads loads 16 x 16B chunks of B.
__device__ __forceinline__ void load_stage_b(uint32_t sbase, int kt,
                                             int n0, int ptid) {
    int koff = kt * BK;
#pragma unroll
    for (int j = 0; j < 16; j++) {
        int i = ptid + j * N_PRODUCER_THREADS;    // 0..2047
        int r = i >> 3;
        int c = i & 7;
        uint32_t soff = SWZ128((uint32_t)(r * 128 + c * 16));
        size_t gb = (size_t)(n0 + r) * K_DIM + koff + c * 8;
        cp16(sbase + soff, g_W_h + gb);
    }
}
#endif

__global__ void __launch_bounds__(GEMM_THREADS)
lstm_gemm_kernel(const float* __restrict__ c_in,
                 const float* __restrict__ bi, const float* __restrict__ bf_,
                 const float* __restrict__ bg, const float* __restrict__ bo,
                 float* __restrict__ out) {
    extern __shared__ char smem[];
    int tid = threadIdx.x;
    const size_t c_off = (size_t)B_DIM * U_DIM;

    // tiles owned by this CTA (persistent): exactly 8 at GRID_X=128
    int tiles[MAX_TILES_PER_CTA];
    int ntiles = 0;
    for (int t = blockIdx.x; t < NTILES_TOTAL && ntiles < MAX_TILES_PER_CTA;
         t += GRID_X)
        tiles[ntiles++] = t;
    if (ntiles == 0) return;

#if USE_TCGEN05
    // ======================= warp-specialized TS path =======================
    uint32_t sb = smem_u32(smem);
    int wid = tid >> 5;
    int lid = tid & 31;

    if (wid == 0) TCGEN05_ALLOC(sb + SM_TMEM, 512);
    if (tid == 0) {
#pragma unroll
        for (int s = 0; s < NSTAGES; s++) {
            MBARRIER_INIT(sb + SM_FULL + 8 * s, N_PRODUCER_THREADS);
            MBARRIER_INIT(sb + SM_MMAB + 8 * s, 1);
        }
    }
    __syncthreads();
    uint32_t tmem;
    asm volatile("ld.shared.b32 %0, [%1];" : "=r"(tmem) : "r"(sb + SM_TMEM));

    const int G = ntiles * KTILES;

    if (wid >= 4) {
        // =================== PRODUCER warps 4-7: B only =====================
        int ptid = tid - 128;    // 0..127

#pragma unroll 1
        for (int gp = 0; gp < G; gp++) {
            if (gp >= NSTAGES) {
                int w = gp - NSTAGES;
                MBARRIER_WAIT_PARITY(sb + SM_MMAB + 8 * (w % NSTAGES),
                                     (w / NSTAGES) & 1);
            }
            int t2 = tiles[gp >> 5];                // KTILES == 32
            int kt2 = gp & 31;
            int n02 = (t2 & (NTILES_N - 1)) * BN;
            load_stage_b(sb + SM_STAGE + (gp % NSTAGES) * STAGE_BYTES,
                         kt2, n02, ptid);
            CP_ASYNC_MBAR_ARRIVE(sb + SM_FULL + 8 * (gp % NSTAGES));
        }

    } else {
        // ============ CONSUMER warps 0-3: A->TMEM + MMA + epilogue ==========
        int row_in_tile = wid * 32 + lid;           // 0..127
        uint32_t warp_off = (uint32_t)wid << 21;    // TMEM subpartition

        // prefetch A for g=0 (tile 0, kt 0): 64 halfs = 128B = 8 x uint4
        uint32_t apf[32];
        {
            int m00 = (tiles[0] >> 4) * BM;
            const uint4* src = reinterpret_cast<const uint4*>(
                g_A_h + (size_t)(m00 + row_in_tile) * K_DIM);
#pragma unroll
            for (int q = 0; q < 8; q++)
                *reinterpret_cast<uint4*>(apf + 4 * q) = src[q];
        }

        int g = 0;
#pragma unroll 1
        for (int j = 0; j < ntiles; j++) {
            int t = tiles[j];
            int m0 = (t >> 4) * BM;
            int n0 = (t & (NTILES_N - 1)) * BN;
            int u_base = n0 >> 2;

#pragma unroll 1
            for (int kt = 0; kt < KTILES; kt++, g++) {
                // A TMEM slot g%4 was read by MMA(g-4): wait its commit
                if (g >= NSTAGES) {
                    int w = g - NSTAGES;
                    MBARRIER_WAIT_PARITY(sb + SM_MMAB + 8 * (w % NSTAGES),
                                         (w / NSTAGES) & 1);
                }
                // store A(g) regs -> TMEM slot (warp-collective, 32 cols)
                TCGEN05_ST_32X32B_X32(
                    tmem + TMEM_A_OFF + (g % NSTAGES) * 32 + warp_off, apf);
                TCGEN05_WAIT_ST();
                TCGEN05_FENCE_BEFORE();

                // prefetch A(g+1)
                if (g + 1 < G) {
                    int t2 = tiles[(g + 1) >> 5];
                    int kt2 = (g + 1) & 31;
                    int m02 = (t2 >> 4) * BM;
                    const uint4* src = reinterpret_cast<const uint4*>(
                        g_A_h + (size_t)(m02 + row_in_tile) * K_DIM + kt2 * BK);
#pragma unroll
                    for (int q = 0; q < 8; q++)
                        *reinterpret_cast<uint4*>(apf + 4 * q) = src[q];
                }

                // all 4 warps' STTM visible before MMA reads the slot
                NAMED_BARRIER_SYNC(1, 128);

                if (wid == 0) {
                    MBARRIER_WAIT_PARITY(sb + SM_FULL + 8 * (g % NSTAGES),
                                         (g / NSTAGES) & 1);
                    uint32_t aslot = tmem + TMEM_A_OFF + (g % NSTAGES) * 32;
                    uint64_t dB = make_desc(
                        sb + SM_STAGE + (g % NSTAGES) * STAGE_BYTES);
                    if (elect_one()) {
                        TCGEN05_FENCE_AFTER();
                        FENCE_PROXY_ASYNC();
#pragma unroll
                        for (int s = 0; s < 4; s++) {  // 4 x K=16 steps
                            mma_f16_ts(tmem, aslot + s * 8, dB + s * 2,
                                       MMA_IDESC, (kt | s) != 0);
                        }
                        TCGEN05_COMMIT(sb + SM_MMAB + 8 * (g % NSTAGES));
                    }
                }
            }

            // ---- tile epilogue: wait last commit, read D, fused LSTM ------
            {
                int gl = g - 1;
                MBARRIER_WAIT_PARITY(sb + SM_MMAB + 8 * (gl % NSTAGES),
                                     (gl / NSTAGES) & 1);
            }
            TCGEN05_FENCE_AFTER();

            int m = m0 + row_in_tile;
            const float* crow = c_in + (size_t)m * U_DIM;
            float* hrow = out + (size_t)m * U_DIM;
            float* corow = out + c_off + (size_t)m * U_DIM;
#pragma unroll
            for (int ch = 0; ch < 8; ch++) {
                uint32_t col = (uint32_t)(ch * 32);
                uint32_t d[32];
                TCGEN05_LD_32X32B_X32(d, tmem + col);
                int u0c = u_base + ch * 8;
                float4 cv0 = *reinterpret_cast<const float4*>(crow + u0c);
                float4 cv1 = *reinterpret_cast<const float4*>(crow + u0c + 4);
                float cvs[8] = {cv0.x, cv0.y, cv0.z, cv0.w,
                                cv1.x, cv1.y, cv1.z, cv1.w};
                TCGEN05_WAIT_LD();
                float hv[8], cnv[8];
#pragma unroll
                for (int q = 0; q < 8; q++) {
                    int u = u0c + q;
                    float zi = __uint_as_float(d[4 * q + 0]) + bi[u];
                    float zf = __uint_as_float(d[4 * q + 1]) + bf_[u];
                    float zg = __uint_as_float(d[4 * q + 2]) + bg[u];
                    float zo = __uint_as_float(d[4 * q + 3]) + bo[u];
                    float ig = fast_sigmoid(zi);
                    float fg = fast_sigmoid(zf);
                    float gg = tanh_fast(zg);
                    float og = fast_sigmoid(zo);
                    float cn = fg * cvs[q] + ig * gg;
                    hv[q] = og * tanh_fast(cn);
                    cnv[q] = cn;
                }
                *reinterpret_cast<float4*>(hrow + u0c) =
                    make_float4(hv[0], hv[1], hv[2], hv[3]);
                *reinterpret_cast<float4*>(hrow + u0c + 4) =
                    make_float4(hv[4], hv[5], hv[6], hv[7]);
                *reinterpret_cast<float4*>(corow + u0c) =
                    make_float4(cnv[0], cnv[1], cnv[2], cnv[3]);
                *reinterpret_cast<float4*>(corow + u0c + 4) =
                    make_float4(cnv[4], cnv[5], cnv[6], cnv[7]);
            }
            TCGEN05_WAIT_LD();
            TCGEN05_FENCE_BEFORE();
            // all warps 0-3 done reading D before next tile's acc=0 MMA
            NAMED_BARRIER_SYNC(1, 128);
        }
    }

    __syncthreads();
    if (tid == 0) {
#pragma unroll
        for (int s = 0; s < NSTAGES; s++) {
            MBARRIER_INVAL(sb + SM_FULL + 8 * s);
            MBARRIER_INVAL(sb + SM_MMAB + 8 * s);
        }
    }
    __syncthreads();
    if (wid == 0) TCGEN05_DEALLOC(tmem, 512);

#else
    // ======================= SIMT fallback (plain sm_103 target) ===========
    const int PAD = 132;
    float* As = reinterpret_cast<float*>(smem);          // [32][PAD]
    float* Bs = As + 32 * PAD;                           // [32][PAD]

    int tx = tid & 15;
    int ty = tid >> 4;

#pragma unroll 1
    for (int j = 0; j < ntiles; j++) {
        int t = tiles[j];
        int m0 = (t >> 4) * BM;
        int n0 = (t & (NTILES_N - 1)) * BN;

#pragma unroll 1
        for (int ns = 0; ns < 2; ns++) {
            int n0h = n0 + ns * 128;
            int u0 = n0h >> 2;
            float acc[8][8];
#pragma unroll
            for (int i = 0; i < 8; i++)
#pragma unroll
                for (int q = 0; q < 8; q++) acc[i][q] = 0.0f;

#pragma unroll 1
            for (int kt = 0; kt < K_DIM / 32; kt++) {
                int koff = kt * 32;
#pragma unroll
                for (int i = 0; i < 16; i++) {
                    int idx = tid + i * 256;
                    int kk = idx & 31;
                    int r = idx >> 5;
                    size_t ga = (size_t)(m0 + r) * K_DIM + koff + kk;
                    size_t gb = (size_t)(n0h + r) * K_DIM + koff + kk;
                    As[kk * PAD + r] = __half2float(g_A_h[ga]);
                    Bs[kk * PAD + r] = __half2float(g_W_h[gb]);
                }
                __syncthreads();
#pragma unroll 1
                for (int kk = 0; kk < 32; kk++) {
                    float a[8], b[8];
#pragma unroll
                    for (int i = 0; i < 8; i++) a[i] = As[kk * PAD + ty * 8 + i];
#pragma unroll
                    for (int q = 0; q < 8; q++) b[q] = Bs[kk * PAD + tx * 8 + q];
#pragma unroll
                    for (int i = 0; i < 8; i++)
#pragma unroll
                        for (int q = 0; q < 8; q++) acc[i][q] += a[i] * b[q];
                }
                __syncthreads();
            }

#pragma unroll
            for (int i = 0; i < 8; i++) {
                int m = m0 + ty * 8 + i;
#pragma unroll
                for (int jj = 0; jj < 2; jj++) {
                    int u = u0 + tx * 2 + jj;
                    float zi = acc[i][jj * 4 + 0] + bi[u];
                    float zf = acc[i][jj * 4 + 1] + bf_[u];
                    float zg = acc[i][jj * 4 + 2] + bg[u];
                    float zo = acc[i][jj * 4 + 3] + bo[u];
                    float ig = fast_sigmoid(zi);
                    float fg = fast_sigmoid(zf);
                    float gg = tanh_fast(zg);
                    float og = fast_sigmoid(zo);
                    float cv = c_in[(size_t)m * U_DIM + u];
                    float cn = fg * cv + ig * gg;
                    float hn = og * tanh_fast(cn);
                    out[(size_t)m * U_DIM + u] = hn;
                    out[c_off + (size_t)m * U_DIM + u] = cn;
                }
            }
            __syncthreads();
        }
    }
#endif
}

// ---------------- launch ----------------------------------------------------
extern "C" void kernel_launch(void* const* d_in, const int* in_sizes, int n_in,
                              void* d_out, int out_size) {
    const float* x  = (const float*)d_in[0];
    const float* h  = (const float*)d_in[1];
    const float* c  = (const float*)d_in[2];
    const float* Wi = (const float*)d_in[3];
    const float* Wf = (const float*)d_in[4];
    const float* Wg = (const float*)d_in[5];
    const float* Wo = (const float*)d_in[6];
    const float* bi = (const float*)d_in[7];
    const float* bf = (const float*)d_in[8];
    const float* bg = (const float*)d_in[9];
    const float* bo = (const float*)d_in[10];
    float* out = (float*)d_out;

    // 1) fused prep: concat->fp16 A  +  W transpose->fp16 (one launch)
    prep_fused_kernel<<<PREP_A_BLOCKS + PREP_W_BLOCKS, 256>>>(
        x, h, Wi, Wf, Wg, Wo);
    // 2) persistent TS-mode GEMM + LSTM epilogue
    cudaFuncSetAttribute(lstm_gemm_kernel,
                         cudaFuncAttributeMaxDynamicSharedMemorySize, GEMM_SMEM);
    lstm_gemm_kernel<<<GRID_X, GEMM_THREADS, GEMM_SMEM>>>(
        c, bi, bf, bg, bo, out);
}

// round 15
// speedup vs baseline: 1.3358x; 1.3358x over previous
#include <cuda_runtime.h>
#include <cuda_fp16.h>
#include <cstdint>

// ============================================================================
// CellLSTM on GB300 (sm_103a)
//   z = [x|h] @ [Wi|Wf|Wg|Wo] + b ; gates; c' = f*c + i*g ; h' = o*tanh(c')
//   R15: TS-mode MMA with PRODUCER-side A feed. R14 proved TS numerics but
//   serialized the consumer (STTM+barrier per iter on MMA path -> 348us).
//   Now: producers (warps 4-7) do A LDG->STTM + B cp.async, signal fullA/fullB;
//   consumer warp 0 only waits + issues 4 TS dispatches (B-only SMEM fetch =
//   512cyc floor vs SS's ~1600). A prep emits [tile][kt][j][row] 16B chunks so
//   producer LDGs are fully coalesced.
// ============================================================================

#if defined(__CUDA_ARCH_FEAT_SM103_ALL) || defined(__CUDA_ARCH_FEAT_SM100_ALL)
#define USE_TCGEN05 1
#else
#define USE_TCGEN05 0
#endif

#define B_DIM 8192
#define T_DIM 1024
#define U_DIM 1024
#define K_DIM 2048
#define N_DIM 4096

#define BM 128
#define BN 256
#define BK 64
#define KTILES (K_DIM / BK)         // 32 k-iterations per tile
#define NTILES_TOTAL ((B_DIM / BM) * (N_DIM / BN))   // 64*16 = 1024
#define NTILES_N (N_DIM / BN)       // 16
#define GRID_X 128                  // 1024 tiles / 128 = exactly 8 per CTA
#define MAX_TILES_PER_CTA 8
#define GEMM_THREADS 256

// ---------------- scratch (device globals: allocation-rule-safe) -----------
// A in TS-native layout: 16B chunk index = ((tile_m*32 + kt)*8 + j)*128 + r
//   tile_m = m>>7, r = m&127, kt = k>>6, j = (k>>3)&7, elem = k&7
__device__ __align__(16) __half g_A_t[(size_t)B_DIM * K_DIM];
// W transposed & gate-interleaved: row n = u*4 + gate, K-major
__device__ __align__(16) __half g_W_h[(size_t)N_DIM * K_DIM];

// ---------------- arch-neutral helpers -------------------------------------
__device__ __forceinline__ uint32_t smem_u32(const void* p) {
    uint32_t a;
    asm("{ .reg .u64 t; cvta.to.shared.u64 t, %1; cvt.u32.u64 %0, t; }"
        : "=r"(a) : "l"(p));
    return a;
}

#define SWZ128(off) ((off) ^ (((off) >> 3) & 0x70))

__device__ __forceinline__ float tanh_fast(float x) {
    float y;
    asm("tanh.approx.f32 %0, %1;" : "=f"(y) : "f"(x));
    return y;
}

__device__ __forceinline__ float fast_sigmoid(float z) {
    return fmaf(0.5f, tanh_fast(0.5f * z), 0.5f);
}

#if USE_TCGEN05
// ---------------- tcgen05 / mbarrier / cp.async helpers --------------------
__device__ __forceinline__ uint32_t elect_one() {
    uint32_t pred;
    asm volatile(
        "{\n\t.reg .pred p;\n\telect.sync _|p, 0xFFFFFFFF;\n\t"
        "selp.b32 %0, 1, 0, p;\n\t}" : "=r"(pred));
    return pred;
}

#define MBARRIER_INIT(addr, cnt) \
    asm volatile("mbarrier.init.shared.b64 [%0], %1;" \
                 :: "r"((uint32_t)(addr)), "r"((uint32_t)(cnt)) : "memory")

#define MBARRIER_INVAL(addr) \
    asm volatile("mbarrier.inval.shared.b64 [%0];" \
                 :: "r"((uint32_t)(addr)) : "memory")

#define MBARRIER_ARRIVE(addr) \
    asm volatile("mbarrier.arrive.shared.b64 _, [%0];" \
                 :: "r"((uint32_t)(addr)) : "memory")

#define CP_ASYNC_MBAR_ARRIVE(addr) \
    asm volatile("cp.async.mbarrier.arrive.noinc.shared::cta.b64 [%0];" \
                 :: "r"((uint32_t)(addr)) : "memory")

#define MBARRIER_WAIT_PARITY(mbar_smem_addr, phase_parity) do { \
    uint32_t _mbar = (uint32_t)(mbar_smem_addr); \
    uint32_t _parity = (uint32_t)(phase_parity); \
    uint32_t _done; \
    asm volatile( \
        "{\n\t.reg .pred p;\n\t" \
        "mbarrier.try_wait.parity.acquire.cta.shared::cta.b64 p, [%1], %2;\n\t" \
        "selp.b32 %0, 1, 0, p;\n\t}" \
        : "=r"(_done) : "r"(_mbar), "r"(_parity) : "memory"); \
    if (!_done) { \
        asm volatile( \
            "{\n\t.reg .pred P1;\n\t" \
            "WAIT_LOOP_%=:\n\t" \
            "mbarrier.try_wait.parity.acquire.cta.shared::cta.b64 P1, [%0], %1, 0x989680;\n\t" \
            "@P1 bra.uni WAIT_DONE_%=;\n\t" \
            "bra.uni WAIT_LOOP_%=;\n\t" \
            "WAIT_DONE_%=:\n\t}" \
            :: "r"(_mbar), "r"(_parity) : "memory"); \
    } \
} while (0)

#define NAMED_BARRIER_SYNC(id, cnt) \
    asm volatile("bar.sync %0, %1;" :: "r"(id), "r"(cnt) : "memory")

#define TCGEN05_ALLOC(smem_result_addr, nCols) \
    asm volatile("tcgen05.alloc.cta_group::1.sync.aligned.shared::cta.b32 [%0], %1;" \
                 :: "r"((uint32_t)(smem_result_addr)), "r"((uint32_t)(nCols)) : "memory")

#define TCGEN05_DEALLOC(tmem_addr, nCols) \
    asm volatile("tcgen05.dealloc.cta_group::1.sync.aligned.b32 %0, %1;" \
                 :: "r"(tmem_addr), "r"((uint32_t)(nCols)))

#define TCGEN05_COMMIT(mbar_smem_addr) \
    asm volatile("tcgen05.commit.cta_group::1.mbarrier::arrive::one.shared::cluster.b64 [%0];" \
                 :: "r"((uint32_t)(mbar_smem_addr)) : "memory")

#define TCGEN05_FENCE_AFTER() \
    asm volatile("tcgen05.fence::after_thread_sync;" ::: "memory")
#define TCGEN05_FENCE_BEFORE() \
    asm volatile("tcgen05.fence::before_thread_sync;" ::: "memory")
#define TCGEN05_WAIT_LD() \
    asm volatile("tcgen05.wait::ld.sync.aligned;" ::: "memory")
#define TCGEN05_WAIT_ST() \
    asm volatile("tcgen05.wait::st.sync.aligned;" ::: "memory")

#define FENCE_PROXY_ASYNC() \
    asm volatile("fence.proxy.async.shared::cta;" ::: "memory")

__device__ __forceinline__ void cp16(uint32_t dst, const void* src) {
    asm volatile("cp.async.cg.shared.global [%0], [%1], 16;"
                 :: "r"(dst), "l"(src) : "memory");
}

#define TCGEN05_LD_32X32B_X32(r, tmem_addr) \
    asm volatile( \
        "tcgen05.ld.sync.aligned.32x32b.x32.b32 " \
        "{%0, %1, %2, %3, %4, %5, %6, %7, " \
        " %8, %9, %10, %11, %12, %13, %14, %15, " \
        " %16, %17, %18, %19, %20, %21, %22, %23, " \
        " %24, %25, %26, %27, %28, %29, %30, %31}, [%32];" \
        : "=r"((r)[0]),  "=r"((r)[1]),  "=r"((r)[2]),  "=r"((r)[3]), \
          "=r"((r)[4]),  "=r"((r)[5]),  "=r"((r)[6]),  "=r"((r)[7]), \
          "=r"((r)[8]),  "=r"((r)[9]),  "=r"((r)[10]), "=r"((r)[11]), \
          "=r"((r)[12]), "=r"((r)[13]), "=r"((r)[14]), "=r"((r)[15]), \
          "=r"((r)[16]), "=r"((r)[17]), "=r"((r)[18]), "=r"((r)[19]), \
          "=r"((r)[20]), "=r"((r)[21]), "=r"((r)[22]), "=r"((r)[23]), \
          "=r"((r)[24]), "=r"((r)[25]), "=r"((r)[26]), "=r"((r)[27]), \
          "=r"((r)[28]), "=r"((r)[29]), "=r"((r)[30]), "=r"((r)[31]) \
        : "r"(tmem_addr))

#define TCGEN05_ST_32X32B_X32(tmem_addr, r) \
    asm volatile( \
        "tcgen05.st.sync.aligned.32x32b.x32.b32 [%0], " \
        "{%1, %2, %3, %4, %5, %6, %7, %8, " \
        " %9, %10, %11, %12, %13, %14, %15, %16, " \
        " %17, %18, %19, %20, %21, %22, %23, %24, " \
        " %25, %26, %27, %28, %29, %30, %31, %32};" \
        :: "r"(tmem_addr), \
           "r"((r)[0]),  "r"((r)[1]),  "r"((r)[2]),  "r"((r)[3]), \
           "r"((r)[4]),  "r"((r)[5]),  "r"((r)[6]),  "r"((r)[7]), \
           "r"((r)[8]),  "r"((r)[9]),  "r"((r)[10]), "r"((r)[11]), \
           "r"((r)[12]), "r"((r)[13]), "r"((r)[14]), "r"((r)[15]), \
           "r"((r)[16]), "r"((r)[17]), "r"((r)[18]), "r"((r)[19]), \
           "r"((r)[20]), "r"((r)[21]), "r"((r)[22]), "r"((r)[23]), \
           "r"((r)[24]), "r"((r)[25]), "r"((r)[26]), "r"((r)[27]), \
           "r"((r)[28]), "r"((r)[29]), "r"((r)[30]), "r"((r)[31]) \
        : "memory")

// K-major SW128 smem descriptor (verified: test_mma_iter)
static constexpr uint64_t SMEM_DESC_BASE_SW128 =
    (uint64_t(2)  << 61) | (uint64_t(1) << 46) |
    (uint64_t(64) << 32) | (uint64_t(1) << 16);

__device__ __forceinline__ uint64_t make_desc(uint32_t addr) {
    return SMEM_DESC_BASE_SW128 | ((uint64_t)(addr >> 4) & 0x3FFF);
}

// idesc kind::f16, FP16 inputs, f32 accum, M=128, N=256
static constexpr uint32_t MMA_IDESC =
    (1u << 4) | (0u << 7) | (0u << 10) | ((BN / 8) << 17) | ((BM / 16) << 24);

// TS form: A in TMEM (numerically verified in R14)
__device__ __forceinline__ void mma_f16_ts(uint32_t d, uint32_t a_tmem,
                                           uint64_t bd, uint32_t idesc,
                                           uint32_t acc) {
    asm volatile(
        "{\n\t.reg .pred p;\n\t"
        "setp.ne.u32 p, %4, 0;\n\t"
        "tcgen05.mma.cta_group::1.kind::f16 [%0], [%1], %2, %3, {%5, %5, %5, %5}, p;\n\t"
        "}"
        :: "r"(d), "r"(a_tmem), "l"(bd), "r"(idesc), "r"(acc), "r"(0u)
        : "memory");
}
#endif // USE_TCGEN05

// ---------------- fused prep kernel -----------------------------------------
// blocks [0, 2048): A -> fp16, TS layout  (one block per (tile_m, kt))
// blocks [2048, 2048+8192): W transpose+convert (unchanged)
#define PREP_A_BLOCKS ((B_DIM / BM) * KTILES)              // 2048
#define PREP_W_BLOCKS ((K_DIM / 32) * (U_DIM / 32) * 4)    // 8192

__global__ void prep_fused_kernel(const float* __restrict__ x,
                                  const float* __restrict__ h,
                                  const float* __restrict__ Wi,
                                  const float* __restrict__ Wf,
                                  const float* __restrict__ Wg,
                                  const float* __restrict__ Wo) {
    __shared__ float tile[32][33];
    int bid = blockIdx.x;
    int tid = threadIdx.x;

    if (bid < PREP_A_BLOCKS) {
        // ---- A path: (tile_m, kt) block -> 128 rows x 64 k, TS layout ----
        int tile_m = bid >> 5;             // 0..63
        int kt = bid & 31;                 // 0..31
        int m0 = tile_m * BM;
        int k0 = kt * BK;                  // multiple of 64, never straddles x/h

        const size_t base_chunk = ((size_t)(tile_m * 32 + kt)) * 8 * 128;
#pragma unroll
        for (int i = 0; i < 4; i++) {
            int cid = tid + i * 256;       // 0..1023
            int jj = cid & 7;              // k-octet
            int r = cid >> 3;              // row
            int m = m0 + r;
            int k = k0 + jj * 8;
            const float* src = (k < T_DIM)
                ? (x + (size_t)m * T_DIM + k)
                : (h + (size_t)m * U_DIM + (k - T_DIM));
            float4 v0 = *reinterpret_cast<const float4*>(src);
            float4 v1 = *reinterpret_cast<const float4*>(src + 4);

            union Pack { __half b[8]; uint4 u; } p;
            p.b[0] = __float2half_rn(v0.x); p.b[1] = __float2half_rn(v0.y);
            p.b[2] = __float2half_rn(v0.z); p.b[3] = __float2half_rn(v0.w);
            p.b[4] = __float2half_rn(v1.x); p.b[5] = __float2half_rn(v1.y);
            p.b[6] = __float2half_rn(v1.z); p.b[7] = __float2half_rn(v1.w);
            size_t chunk = base_chunk + (size_t)jj * 128 + r;
            *reinterpret_cast<uint4*>(g_A_t + chunk * 8) = p.u;
        }
    } else {
        // ---- W path: 32x32 transpose tile per block ----
        int w = bid - PREP_A_BLOCKS;       // 0..8191
        int gate = w >> 11;
        int rem = w & 2047;
        int k0 = (rem & 63) * 32;
        int u0 = (rem >> 6) * 32;
        const float* W = (gate == 0) ? Wi : (gate == 1) ? Wf
                        : (gate == 2) ? Wg : Wo;
        int tx = tid & 31;
        int ty = tid >> 5;

#pragma unroll
        for (int i = 0; i < 4; i++) {
            int k = k0 + ty + i * 8;
            tile[ty + i * 8][tx] = W[(size_t)k * U_DIM + u0 + tx];
        }
        __syncthreads();
#pragma unroll
        for (int i = 0; i < 4; i++) {
            int u = u0 + ty + i * 8;
            float v = tile[tx][ty + i * 8];
            size_t off = (size_t)(u * 4 + gate) * K_DIM + k0 + tx;
            g_W_h[off] = __float2half_rn(v);
        }
    }
}

// ---------------- GEMM + LSTM epilogue -------------------------------------
// SMEM map:
//   [0]      tmem ptr
//   [8]      fullA[4] mbarriers (count 128) -- producers' STTM complete
//   [64]     fullB[4] mbarriers (count 128) -- cp.async B landed
//   [128]    mma[4]   mbarriers (count 1)   -- MMA commit frees both slots
//   [1024]   4 stages x B(32KB) = 128KB ring (SW128, 256 rows x 128B)
// TMEM map: D = cols 0..255 (fp32), A slots = 4 x 32 cols at 256..383
#define SM_TMEM 0
#define SM_FULLA 8
#define SM_FULLB 64
#define SM_MMAB 128
#define SM_STAGE 1024
#define B_TILE_BYTES 32768
#define STAGE_BYTES B_TILE_BYTES
#define NSTAGES 4
#define GEMM_SMEM (SM_STAGE + NSTAGES * STAGE_BYTES)        // 132096
#define TMEM_A_OFF 256
#define N_PRODUCER_THREADS 128

__global__ void __launch_bounds__(GEMM_THREADS)
lstm_gemm_kernel(const float* __restrict__ c_in,
                 const float* __restrict__ bi, const float* __restrict__ bf_,
                 const float* __restrict__ bg, const float* __restrict__ bo,
                 float* __restrict__ out) {
    extern __shared__ char smem[];
    int tid = threadIdx.x;
    const size_t c_off = (size_t)B_DIM * U_DIM;

    int tiles[MAX_TILES_PER_CTA];
    int ntiles = 0;
    for (int t = blockIdx.x; t < NTILES_TOTAL && ntiles < MAX_TILES_PER_CTA;
         t += GRID_X)
        tiles[ntiles++] = t;
    if (ntiles == 0) return;

#if USE_TCGEN05
    // ======================= warp-specialized TS path =======================
    uint32_t sb = smem_u32(smem);
    int wid = tid >> 5;
    int lid = tid & 31;

    if (wid == 0) TCGEN05_ALLOC(sb + SM_TMEM, 512);
    if (tid == 0) {
#pragma unroll
        for (int s = 0; s < NSTAGES; s++) {
            MBARRIER_INIT(sb + SM_FULLA + 8 * s, N_PRODUCER_THREADS);
            MBARRIER_INIT(sb + SM_FULLB + 8 * s, N_PRODUCER_THREADS);
            MBARRIER_INIT(sb + SM_MMAB + 8 * s, 1);
        }
    }
    __syncthreads();
    uint32_t tmem;
    asm volatile("ld.shared.b32 %0, [%1];" : "=r"(tmem) : "r"(sb + SM_TMEM));

    const int G = ntiles * KTILES;

    if (wid >= 4) {
        // ============ PRODUCER warps 4-7: A (LDG->STTM) + B (cp.async) ======
        int ptid = tid - 128;                      // 0..127 = A row in tile
        uint32_t warp_off = (uint32_t)(ptid >> 5) << 21;

        // prefetch A(0): coalesced 8 x uint4 from TS layout
        uint32_t apf[32];
        {
            int t0 = tiles[0];
            size_t base = ((size_t)((t0 >> 4) * 32 + 0)) * 8 * 128;  // kt = 0
#pragma unroll
            for (int q = 0; q < 8; q++)
                *reinterpret_cast<uint4*>(apf + 4 * q) =
                    *reinterpret_cast<const uint4*>(
                        g_A_t + (base + (size_t)q * 128 + ptid) * 8);
        }

#pragma unroll 1
        for (int gp = 0; gp < G; gp++) {
            // slot gp%4 (A TMEM + B SMEM) freed by MMA(gp-4)
            if (gp >= NSTAGES) {
                int w = gp - NSTAGES;
                MBARRIER_WAIT_PARITY(sb + SM_MMAB + 8 * (w % NSTAGES),
                                     (w / NSTAGES) & 1);
            }
            // A(gp): regs -> TMEM slot
            TCGEN05_ST_32X32B_X32(
                tmem + TMEM_A_OFF + (gp % NSTAGES) * 32 + warp_off, apf);
            TCGEN05_WAIT_ST();
            TCGEN05_FENCE_BEFORE();
            MBARRIER_ARRIVE(sb + SM_FULLA + 8 * (gp % NSTAGES));

            // prefetch A(gp+1) (latency hidden by the rest of this iteration)
            if (gp + 1 < G) {
                int t2 = tiles[(gp + 1) >> 5];
                int kt2 = (gp + 1) & 31;
                size_t base = ((size_t)((t2 >> 4) * 32 + kt2)) * 8 * 128;
#pragma unroll
                for (int q = 0; q < 8; q++)
                    *reinterpret_cast<uint4*>(apf + 4 * q) =
                        *reinterpret_cast<const uint4*>(
                            g_A_t + (base + (size_t)q * 128 + ptid) * 8);
            }

            // B(gp): 16 x cp16 per thread
            {
                int t2 = tiles[gp >> 5];
                int kt2 = gp & 31;
                int n02 = (t2 & (NTILES_N - 1)) * BN;
                int koff = kt2 * BK;
                uint32_t sbase = sb + SM_STAGE + (gp % NSTAGES) * STAGE_BYTES;
#pragma unroll
                for (int j = 0; j < 16; j++) {
                    int i = ptid + j * N_PRODUCER_THREADS;
                    int r = i >> 3;
                    int c = i & 7;
                    uint32_t soff = SWZ128((uint32_t)(r * 128 + c * 16));
                    size_t gb = (size_t)(n02 + r) * K_DIM + koff + c * 8;
                    cp16(sbase + soff, g_W_h + gb);
                }
                CP_ASYNC_MBAR_ARRIVE(sb + SM_FULLB + 8 * (gp % NSTAGES));
            }
        }

    } else {
        // ============ CONSUMER warps 0-3: MMA issue (warp 0) + epilogue =====
        int row_in_tile = wid * 32 + lid;          // 0..127
        int g = 0;
#pragma unroll 1
        for (int j = 0; j < ntiles; j++) {
            int t = tiles[j];
            int m0 = (t >> 4) * BM;
            int n0 = (t & (NTILES_N - 1)) * BN;
            int u_base = n0 >> 2;

            if (wid == 0) {
#pragma unroll 1
                for (int kt = 0; kt < KTILES; kt++, g++) {
                    MBARRIER_WAIT_PARITY(sb + SM_FULLA + 8 * (g % NSTAGES),
                                         (g / NSTAGES) & 1);
                    MBARRIER_WAIT_PARITY(sb + SM_FULLB + 8 * (g % NSTAGES),
                                         (g / NSTAGES) & 1);
                    uint32_t aslot = tmem + TMEM_A_OFF + (g % NSTAGES) * 32;
                    uint64_t dB = make_desc(
                        sb + SM_STAGE + (g % NSTAGES) * STAGE_BYTES);
                    if (elect_one()) {
                        TCGEN05_FENCE_AFTER();
                        FENCE_PROXY_ASYNC();
#pragma unroll
                        for (int s = 0; s < 4; s++) {
                            mma_f16_ts(tmem, aslot + s * 8, dB + s * 2,
                                       MMA_IDESC, (kt | s) != 0);
                        }
                        TCGEN05_COMMIT(sb + SM_MMAB + 8 * (g % NSTAGES));
                    }
                }
                int gl = g - 1;
                MBARRIER_WAIT_PARITY(sb + SM_MMAB + 8 * (gl % NSTAGES),
                                     (gl / NSTAGES) & 1);
            } else {
                g += KTILES;   // warps 1-3 skip the mainloop
            }

            // warps 0-3 rendezvous; warp 0 arrives after the last commit
            NAMED_BARRIER_SYNC(1, 128);
            TCGEN05_FENCE_AFTER();

            // ------- epilogue (R14-verified): D cols 0..255, fused LSTM -----
            int m = m0 + row_in_tile;
            const float* crow = c_in + (size_t)m * U_DIM;
            float* hrow = out + (size_t)m * U_DIM;
            float* corow = out + c_off + (size_t)m * U_DIM;
#pragma unroll
            for (int ch = 0; ch < 8; ch++) {
                uint32_t col = (uint32_t)(ch * 32);
                uint32_t d[32];
                TCGEN05_LD_32X32B_X32(d, tmem + col);
                int u0c = u_base + ch * 8;
                float4 cv0 = *reinterpret_cast<const float4*>(crow + u0c);
                float4 cv1 = *reinterpret_cast<const float4*>(crow + u0c + 4);
                float cvs[8] = {cv0.x, cv0.y, cv0.z, cv0.w,
                                cv1.x, cv1.y, cv1.z, cv1.w};
                TCGEN05_WAIT_LD();
                float hv[8], cnv[8];
#pragma unroll
                for (int q = 0; q < 8; q++) {
                    int u = u0c + q;
                    float zi = __uint_as_float(d[4 * q + 0]) + bi[u];
                    float zf = __uint_as_float(d[4 * q + 1]) + bf_[u];
                    float zg = __uint_as_float(d[4 * q + 2]) + bg[u];
                    float zo = __uint_as_float(d[4 * q + 3]) + bo[u];
                    float ig = fast_sigmoid(zi);
                    float fg = fast_sigmoid(zf);
                    float gg = tanh_fast(zg);
                    float og = fast_sigmoid(zo);
                    float cn = fg * cvs[q] + ig * gg;
                    hv[q] = og * tanh_fast(cn);
                    cnv[q] = cn;
                }
                *reinterpret_cast<float4*>(hrow + u0c) =
                    make_float4(hv[0], hv[1], hv[2], hv[3]);
                *reinterpret_cast<float4*>(hrow + u0c + 4) =
                    make_float4(hv[4], hv[5], hv[6], hv[7]);
                *reinterpret_cast<float4*>(corow + u0c) =
                    make_float4(cnv[0], cnv[1], cnv[2], cnv[3]);
                *reinterpret_cast<float4*>(corow + u0c + 4) =
                    make_float4(cnv[4], cnv[5], cnv[6], cnv[7]);
            }
            TCGEN05_WAIT_LD();
            TCGEN05_FENCE_BEFORE();
            NAMED_BARRIER_SYNC(1, 128);
        }
    }

    __syncthreads();
    if (tid == 0) {
#pragma unroll
        for (int s = 0; s < NSTAGES; s++) {
            MBARRIER_INVAL(sb + SM_FULLA + 8 * s);
            MBARRIER_INVAL(sb + SM_FULLB + 8 * s);
            MBARRIER_INVAL(sb + SM_MMAB + 8 * s);
        }
    }
    __syncthreads();
    if (wid == 0) TCGEN05_DEALLOC(tmem, 512);

#else
    // ======================= SIMT fallback (plain sm_103 target) ===========
    // Reads A via the TS chunk layout.
    const int PAD = 132;
    float* As = reinterpret_cast<float*>(smem);          // [32][PAD]
    float* Bs = As + 32 * PAD;                           // [32][PAD]

    int tx = tid & 15;
    int ty = tid >> 4;

#pragma unroll 1
    for (int j = 0; j < ntiles; j++) {
        int t = tiles[j];
        int m0 = (t >> 4) * BM;
        int n0 = (t & (NTILES_N - 1)) * BN;
        int tile_m = t >> 4;

#pragma unroll 1
        for (int ns = 0; ns < 2; ns++) {
            int n0h = n0 + ns * 128;
            int u0 = n0h >> 2;
            float acc[8][8];
#pragma unroll
            for (int i = 0; i < 8; i++)
#pragma unroll
                for (int q = 0; q < 8; q++) acc[i][q] = 0.0f;

#pragma unroll 1
            for (int kt2 = 0; kt2 < K_DIM / 32; kt2++) {
                int koff = kt2 * 32;
#pragma unroll
                for (int i = 0; i < 16; i++) {
                    int idx = tid + i * 256;
                    int kk = idx & 31;
                    int r = idx >> 5;
                    int k = koff + kk;
                    size_t achunk = (((size_t)(tile_m * 32 + (k >> 6))) * 8 +
                                     ((k >> 3) & 7)) * 128 + r;
                    As[kk * PAD + r] = __half2float(g_A_t[achunk * 8 + (k & 7)]);
                    size_t gb = (size_t)(n0h + r) * K_DIM + k;
                    Bs[kk * PAD + r] = __half2float(g_W_h[gb]);
                }
                __syncthreads();
#pragma unroll 1
                for (int kk = 0; kk < 32; kk++) {
                    float a[8], b[8];
#pragma unroll
                    for (int i = 0; i < 8; i++) a[i] = As[kk * PAD + ty * 8 + i];
#pragma unroll
                    for (int q = 0; q < 8; q++) b[q] = Bs[kk * PAD + tx * 8 + q];
#pragma unroll
                    for (int i = 0; i < 8; i++)
#pragma unroll
                        for (int q = 0; q < 8; q++) acc[i][q] += a[i] * b[q];
                }
                __syncthreads();
            }

#pragma unroll
            for (int i = 0; i < 8; i++) {
                int m = m0 + ty * 8 + i;
#pragma unroll
                for (int jj = 0; jj < 2; jj++) {
                    int u = u0 + tx * 2 + jj;
                    float zi = acc[i][jj * 4 + 0] + bi[u];
                    float zf = acc[i][jj * 4 + 1] + bf_[u];
                    float zg = acc[i][jj * 4 + 2] + bg[u];
                    float zo = acc[i][jj * 4 + 3] + bo[u];
                    float ig = fast_sigmoid(zi);
                    float fg = fast_sigmoid(zf);
                    float gg = tanh_fast(zg);
                    float og = fast_sigmoid(zo);
                    float cv = c_in[(size_t)m * U_DIM + u];
                    float cn = fg * cv + ig * gg;
                    float hn = og * tanh_fast(cn);
                    out[(size_t)m * U_DIM + u] = hn;
                    out[c_off + (size_t)m * U_DIM + u] = cn;
                }
            }
            __syncthreads();
        }
    }
#endif
}

// ---------------- launch ----------------------------------------------------
extern "C" void kernel_launch(void* const* d_in, const int* in_sizes, int n_in,
                              void* d_out, int out_size) {
    const float* x  = (const float*)d_in[0];
    const float* h  = (const float*)d_in[1];
    const float* c  = (const float*)d_in[2];
    const float* Wi = (const float*)d_in[3];
    const float* Wf = (const float*)d_in[4];
    const float* Wg = (const float*)d_in[5];
    const float* Wo = (const float*)d_in[6];
    const float* bi = (const float*)d_in[7];
    const float* bf = (const float*)d_in[8];
    const float* bg = (const float*)d_in[9];
    const float* bo = (const float*)d_in[10];
    float* out = (float*)d_out;

    // 1) fused prep: A -> fp16 TS layout  +  W transpose -> fp16
    prep_fused_kernel<<<PREP_A_BLOCKS + PREP_W_BLOCKS, 256>>>(
        x, h, Wi, Wf, Wg, Wo);
    // 2) persistent TS-mode GEMM + LSTM epilogue
    cudaFuncSetAttribute(lstm_gemm_kernel,
                         cudaFuncAttributeMaxDynamicSharedMemorySize, GEMM_SMEM);
    lstm_gemm_kernel<<<GRID_X, GEMM_THREADS, GEMM_SMEM>>>(
        c, bi, bf, bg, bo, out);
}

// round 17
// speedup vs baseline: 1.9592x; 1.4666x over previous
#include <cuda_runtime.h>
#include <cuda_fp16.h>
#include <cstdint>

// ============================================================================
// CellLSTM on GB300 (sm_103a)
//   z = [x|h] @ [Wi|Wf|Wg|Wo] + b ; gates; c' = f*c + i*g ; h' = o*tanh(c')
//   R17: R12 SS pipeline + ping-pong D buffers (TMEM cols 0..255 / 256..511
//   by tile parity) so each tile's epilogue overlaps the NEXT tile's MMAs.
//   Alias-safe tile sync: tiledone[2] (extra tcgen05.commit after the tile's
//   last MMA) + epi[2] (count 128) gating D reuse two tiles later. cg2 parked
//   after two failures (R3 slow, R16 deadlock).
// ============================================================================

#if defined(__CUDA_ARCH_FEAT_SM103_ALL) || defined(__CUDA_ARCH_FEAT_SM100_ALL)
#define USE_TCGEN05 1
#else
#define USE_TCGEN05 0
#endif

#define B_DIM 8192
#define T_DIM 1024
#define U_DIM 1024
#define K_DIM 2048
#define N_DIM 4096

#define BM 128
#define BN 256
#define BK 64
#define KTILES (K_DIM / BK)         // 32 k-iterations per tile
#define NTILES_TOTAL ((B_DIM / BM) * (N_DIM / BN))   // 64*16 = 1024
#define NTILES_N (N_DIM / BN)       // 16
#define GRID_X 128                  // 1024 / 128 = exactly 8 tiles per CTA
#define MAX_TILES_PER_CTA 8
#define GEMM_THREADS 256

// ---------------- scratch (device globals: allocation-rule-safe) -----------
__device__ __align__(16) __half g_A_h[(size_t)B_DIM * K_DIM];
// W transposed & gate-interleaved: row n = u*4 + gate, K-major
__device__ __align__(16) __half g_W_h[(size_t)N_DIM * K_DIM];

// ---------------- arch-neutral helpers -------------------------------------
__device__ __forceinline__ uint32_t smem_u32(const void* p) {
    uint32_t a;
    asm("{ .reg .u64 t; cvta.to.shared.u64 t, %1; cvt.u32.u64 %0, t; }"
        : "=r"(a) : "l"(p));
    return a;
}

#define SWZ128(off) ((off) ^ (((off) >> 3) & 0x70))

__device__ __forceinline__ float tanh_fast(float x) {
    float y;
    asm("tanh.approx.f32 %0, %1;" : "=f"(y) : "f"(x));
    return y;
}

__device__ __forceinline__ float fast_sigmoid(float z) {
    return fmaf(0.5f, tanh_fast(0.5f * z), 0.5f);
}

#if USE_TCGEN05
// ---------------- tcgen05 / mbarrier / cp.async helpers --------------------
__device__ __forceinline__ uint32_t elect_one() {
    uint32_t pred;
    asm volatile(
        "{\n\t.reg .pred p;\n\telect.sync _|p, 0xFFFFFFFF;\n\t"
        "selp.b32 %0, 1, 0, p;\n\t}" : "=r"(pred));
    return pred;
}

#define MBARRIER_INIT(addr, cnt) \
    asm volatile("mbarrier.init.shared.b64 [%0], %1;" \
                 :: "r"((uint32_t)(addr)), "r"((uint32_t)(cnt)) : "memory")

#define MBARRIER_INVAL(addr) \
    asm volatile("mbarrier.inval.shared.b64 [%0];" \
                 :: "r"((uint32_t)(addr)) : "memory")

#define MBARRIER_ARRIVE(addr) \
    asm volatile("mbarrier.arrive.shared.b64 _, [%0];" \
                 :: "r"((uint32_t)(addr)) : "memory")

#define CP_ASYNC_MBAR_ARRIVE(addr) \
    asm volatile("cp.async.mbarrier.arrive.noinc.shared::cta.b64 [%0];" \
                 :: "r"((uint32_t)(addr)) : "memory")

#define MBARRIER_WAIT_PARITY(mbar_smem_addr, phase_parity) do { \
    uint32_t _mbar = (uint32_t)(mbar_smem_addr); \
    uint32_t _parity = (uint32_t)(phase_parity); \
    uint32_t _done; \
    asm volatile( \
        "{\n\t.reg .pred p;\n\t" \
        "mbarrier.try_wait.parity.acquire.cta.shared::cta.b64 p, [%1], %2;\n\t" \
        "selp.b32 %0, 1, 0, p;\n\t}" \
        : "=r"(_done) : "r"(_mbar), "r"(_parity) : "memory"); \
    if (!_done) { \
        asm volatile( \
            "{\n\t.reg .pred P1;\n\t" \
            "WAIT_LOOP_%=:\n\t" \
            "mbarrier.try_wait.parity.acquire.cta.shared::cta.b64 P1, [%0], %1, 0x989680;\n\t" \
            "@P1 bra.uni WAIT_DONE_%=;\n\t" \
            "bra.uni WAIT_LOOP_%=;\n\t" \
            "WAIT_DONE_%=:\n\t}" \
            :: "r"(_mbar), "r"(_parity) : "memory"); \
    } \
} while (0)

#define TCGEN05_ALLOC(smem_result_addr, nCols) \
    asm volatile("tcgen05.alloc.cta_group::1.sync.aligned.shared::cta.b32 [%0], %1;" \
                 :: "r"((uint32_t)(smem_result_addr)), "r"((uint32_t)(nCols)) : "memory")

#define TCGEN05_DEALLOC(tmem_addr, nCols) \
    asm volatile("tcgen05.dealloc.cta_group::1.sync.aligned.b32 %0, %1;" \
                 :: "r"(tmem_addr), "r"((uint32_t)(nCols)))

#define TCGEN05_COMMIT(mbar_smem_addr) \
    asm volatile("tcgen05.commit.cta_group::1.mbarrier::arrive::one.shared::cluster.b64 [%0];" \
                 :: "r"((uint32_t)(mbar_smem_addr)) : "memory")

#define TCGEN05_FENCE_AFTER() \
    asm volatile("tcgen05.fence::after_thread_sync;" ::: "memory")
#define TCGEN05_FENCE_BEFORE() \
    asm volatile("tcgen05.fence::before_thread_sync;" ::: "memory")
#define TCGEN05_WAIT_LD() \
    asm volatile("tcgen05.wait::ld.sync.aligned;" ::: "memory")

#define FENCE_PROXY_ASYNC() \
    asm volatile("fence.proxy.async.shared::cta;" ::: "memory")

__device__ __forceinline__ void cp16(uint32_t dst, const void* src) {
    asm volatile("cp.async.cg.shared.global [%0], [%1], 16;"
                 :: "r"(dst), "l"(src) : "memory");
}

#define TCGEN05_LD_32X32B_X32(r, tmem_addr) \
    asm volatile( \
        "tcgen05.ld.sync.aligned.32x32b.x32.b32 " \
        "{%0, %1, %2, %3, %4, %5, %6, %7, " \
        " %8, %9, %10, %11, %12, %13, %14, %15, " \
        " %16, %17, %18, %19, %20, %21, %22, %23, " \
        " %24, %25, %26, %27, %28, %29, %30, %31}, [%32];" \
        : "=r"((r)[0]),  "=r"((r)[1]),  "=r"((r)[2]),  "=r"((r)[3]), \
          "=r"((r)[4]),  "=r"((r)[5]),  "=r"((r)[6]),  "=r"((r)[7]), \
          "=r"((r)[8]),  "=r"((r)[9]),  "=r"((r)[10]), "=r"((r)[11]), \
          "=r"((r)[12]), "=r"((r)[13]), "=r"((r)[14]), "=r"((r)[15]), \
          "=r"((r)[16]), "=r"((r)[17]), "=r"((r)[18]), "=r"((r)[19]), \
          "=r"((r)[20]), "=r"((r)[21]), "=r"((r)[22]), "=r"((r)[23]), \
          "=r"((r)[24]), "=r"((r)[25]), "=r"((r)[26]), "=r"((r)[27]), \
          "=r"((r)[28]), "=r"((r)[29]), "=r"((r)[30]), "=r"((r)[31]) \
        : "r"(tmem_addr))

// K-major SW128 smem descriptor (verified: test_mma_iter)
static constexpr uint64_t SMEM_DESC_BASE_SW128 =
    (uint64_t(2)  << 61) | (uint64_t(1) << 46) |
    (uint64_t(64) << 32) | (uint64_t(1) << 16);

__device__ __forceinline__ uint64_t make_desc(uint32_t addr) {
    return SMEM_DESC_BASE_SW128 | ((uint64_t)(addr >> 4) & 0x3FFF);
}

// idesc kind::f16, FP16 inputs, f32 accum, M=128, N=256 (R5-proven)
static constexpr uint32_t MMA_IDESC =
    (1u << 4) | ((BN / 8) << 17) | ((BM / 16) << 24);

__device__ __forceinline__ void mma_f16_ss(uint32_t d, uint64_t ad, uint64_t bd,
                                           uint32_t idesc, uint32_t acc) {
    asm volatile(
        "{\n\t.reg .pred p;\n\t"
        "setp.ne.u32 p, %4, 0;\n\t"
        "tcgen05.mma.cta_group::1.kind::f16 [%0], %1, %2, %3, {%5, %5, %5, %5}, p;\n\t"
        "}"
        :: "r"(d), "l"(ad), "l"(bd), "r"(idesc), "r"(acc), "r"(0u)
        : "memory");
}
#endif // USE_TCGEN05

// ---------------- fused prep kernel (unchanged from R12) --------------------
#define PREP_A_BLOCKS ((int)(((size_t)B_DIM * K_DIM / 8) / 256))   // 8192
#define PREP_W_BLOCKS ((K_DIM / 32) * (U_DIM / 32) * 4)            // 8192

__global__ void prep_fused_kernel(const float* __restrict__ x,
                                  const float* __restrict__ h,
                                  const float* __restrict__ Wi,
                                  const float* __restrict__ Wf,
                                  const float* __restrict__ Wg,
                                  const float* __restrict__ Wo) {
    __shared__ float tile[32][33];
    int bid = blockIdx.x;
    int tid = threadIdx.x;

    if (bid < PREP_A_BLOCKS) {
        size_t idx8 = ((size_t)bid * 256 + tid) * 8;
        int m = (int)(idx8 / K_DIM);
        int k = (int)(idx8 % K_DIM);
        const float* src = (k < T_DIM) ? (x + (size_t)m * T_DIM + k)
                                       : (h + (size_t)m * U_DIM + (k - T_DIM));
        float4 v0 = *reinterpret_cast<const float4*>(src);
        float4 v1 = *reinterpret_cast<const float4*>(src + 4);

        union Pack { __half b[8]; uint4 u; } p;
        p.b[0] = __float2half_rn(v0.x); p.b[1] = __float2half_rn(v0.y);
        p.b[2] = __float2half_rn(v0.z); p.b[3] = __float2half_rn(v0.w);
        p.b[4] = __float2half_rn(v1.x); p.b[5] = __float2half_rn(v1.y);
        p.b[6] = __float2half_rn(v1.z); p.b[7] = __float2half_rn(v1.w);
        *reinterpret_cast<uint4*>(g_A_h + idx8) = p.u;
    } else {
        int w = bid - PREP_A_BLOCKS;               // 0..8191
        int gate = w >> 11;
        int rem = w & 2047;
        int k0 = (rem & 63) * 32;
        int u0 = (rem >> 6) * 32;
        const float* W = (gate == 0) ? Wi : (gate == 1) ? Wf
                        : (gate == 2) ? Wg : Wo;
        int tx = tid & 31;
        int ty = tid >> 5;

#pragma unroll
        for (int i = 0; i < 4; i++) {
            int k = k0 + ty + i * 8;
            tile[ty + i * 8][tx] = W[(size_t)k * U_DIM + u0 + tx];
        }
        __syncthreads();
#pragma unroll
        for (int i = 0; i < 4; i++) {
            int u = u0 + ty + i * 8;
            float v = tile[tx][ty + i * 8];
            size_t off = (size_t)(u * 4 + gate) * K_DIM + k0 + tx;
            g_W_h[off] = __float2half_rn(v);
        }
    }
}

// ---------------- GEMM + LSTM epilogue -------------------------------------
// SMEM map:
//   [0]      tmem ptr
//   [8]      full[4]      (count 128, cp.async.mbarrier.arrive)
//   [64]     mma[4]       (count 1, commit per g; producers gate lag-4)
//   [128]    tiledone[2]  (count 1, extra commit after each tile's last MMA)
//   [160]    epi[2]       (count 128, warps 0-3 done reading D of that parity)
//   [1024]   4 stages x (A 16KB + B 32KB) = 192KB ring
// TMEM: D ping-pong: cols [0,256) for even tiles, [256,512) for odd tiles
#define SM_TMEM 0
#define SM_FULL 8
#define SM_MMAB 64
#define SM_TDONE 128
#define SM_EPI 160
#define SM_STAGE 1024
#define A_TILE_BYTES 16384                  // 128 rows x 128B
#define B_TILE_BYTES 32768                  // 256 rows x 128B
#define STAGE_BYTES (A_TILE_BYTES + B_TILE_BYTES)           // 49152
#define NSTAGES 4
#define GEMM_SMEM (SM_STAGE + NSTAGES * STAGE_BYTES)        // 197632
#define N_PRODUCER_THREADS 128

__global__ void __launch_bounds__(GEMM_THREADS)
lstm_gemm_kernel(const float* __restrict__ c_in,
                 const float* __restrict__ bi, const float* __restrict__ bf_,
                 const float* __restrict__ bg, const float* __restrict__ bo,
                 float* __restrict__ out) {
    extern __shared__ char smem[];
    int tid = threadIdx.x;
    const size_t c_off = (size_t)B_DIM * U_DIM;

    int tiles[MAX_TILES_PER_CTA];
    int ntiles = 0;
    for (int t = blockIdx.x; t < NTILES_TOTAL && ntiles < MAX_TILES_PER_CTA;
         t += GRID_X)
        tiles[ntiles++] = t;
    if (ntiles == 0) return;

#if USE_TCGEN05
    // ======================= warp-specialized ping-pong path ================
    uint32_t sb = smem_u32(smem);
    int wid = tid >> 5;
    int lid = tid & 31;

    if (wid == 0) TCGEN05_ALLOC(sb + SM_TMEM, 512);
    if (tid == 0) {
#pragma unroll
        for (int s = 0; s < NSTAGES; s++) {
            MBARRIER_INIT(sb + SM_FULL + 8 * s, N_PRODUCER_THREADS);
            MBARRIER_INIT(sb + SM_MMAB + 8 * s, 1);
        }
        MBARRIER_INIT(sb + SM_TDONE + 0, 1);
        MBARRIER_INIT(sb + SM_TDONE + 8, 1);
        MBARRIER_INIT(sb + SM_EPI + 0, 128);
        MBARRIER_INIT(sb + SM_EPI + 8, 128);
    }
    __syncthreads();
    uint32_t tmem;
    asm volatile("ld.shared.b32 %0, [%1];" : "=r"(tmem) : "r"(sb + SM_TMEM));

    const int G = ntiles * KTILES;          // 256

    if (wid >= 4) {
        // =================== PRODUCER warps 4-7: A + B ======================
        int ptid = tid - 128;               // 0..127

#pragma unroll 1
        for (int gp = 0; gp < G; gp++) {
            if (gp >= NSTAGES) {
                int w = gp - NSTAGES;       // lag exactly 4: alias-safe
                MBARRIER_WAIT_PARITY(sb + SM_MMAB + 8 * (w % NSTAGES),
                                     (w / NSTAGES) & 1);
            }
            int t2 = tiles[gp >> 5];        // KTILES == 32
            int kt2 = gp & 31;
            int koff = kt2 * BK;
            int m02 = (t2 >> 4) * BM;
            int n02 = (t2 & (NTILES_N - 1)) * BN;
            uint32_t sbase = sb + SM_STAGE + (gp % NSTAGES) * STAGE_BYTES;
            // A: 128 rows x 8 chunks -> 8 per thread
#pragma unroll
            for (int j = 0; j < 8; j++) {
                int i = ptid + j * N_PRODUCER_THREADS;   // 0..1023
                int r = i >> 3;
                int c = i & 7;
                uint32_t soff = SWZ128((uint32_t)(r * 128 + c * 16));
                cp16(sbase + soff,
                     g_A_h + (size_t)(m02 + r) * K_DIM + koff + c * 8);
            }
            // B: 256 rows x 8 chunks -> 16 per thread
            uint32_t bbase = sbase + A_TILE_BYTES;
#pragma unroll
            for (int j = 0; j < 16; j++) {
                int i = ptid + j * N_PRODUCER_THREADS;   // 0..2047
                int r = i >> 3;
                int c = i & 7;
                uint32_t soff = SWZ128((uint32_t)(r * 128 + c * 16));
                cp16(bbase + soff,
                     g_W_h + (size_t)(n02 + r) * K_DIM + koff + c * 8);
            }
            CP_ASYNC_MBAR_ARRIVE(sb + SM_FULL + 8 * (gp % NSTAGES));
        }

    } else {
        // ========= CONSUMER warps 0-3: warp0 issues, all do epilogue ========
        int row_lane = wid * 32 + lid;      // 0..127 (wid&3 == TMEM subpart)

        // epilogue for tile index jj (this warp's 32 rows)
        auto do_epilogue = [&](int jj) {
            MBARRIER_WAIT_PARITY(sb + SM_TDONE + 8 * (jj & 1), (jj >> 1) & 1);
            TCGEN05_FENCE_AFTER();
            int t = tiles[jj];
            int m0 = (t >> 4) * BM;
            int u_base = ((t & (NTILES_N - 1)) * BN) >> 2;
            uint32_t dbase = tmem + (uint32_t)((jj & 1) * 256);
            int m = m0 + row_lane;
            const float* crow = c_in + (size_t)m * U_DIM;
            float* hrow = out + (size_t)m * U_DIM;
            float* corow = out + c_off + (size_t)m * U_DIM;
#pragma unroll
            for (int ch = 0; ch < 8; ch++) {
                uint32_t d[32];
                TCGEN05_LD_32X32B_X32(d, dbase + (uint32_t)(ch * 32));
                int u0c = u_base + ch * 8;
                float4 cv0 = *reinterpret_cast<const float4*>(crow + u0c);
                float4 cv1 = *reinterpret_cast<const float4*>(crow + u0c + 4);
                float cvs[8] = {cv0.x, cv0.y, cv0.z, cv0.w,
                                cv1.x, cv1.y, cv1.z, cv1.w};
                TCGEN05_WAIT_LD();
                float hv[8], cnv[8];
#pragma unroll
                for (int q = 0; q < 8; q++) {
                    int u = u0c + q;
                    float zi = __uint_as_float(d[4 * q + 0]) + bi[u];
                    float zf = __uint_as_float(d[4 * q + 1]) + bf_[u];
                    float zg = __uint_as_float(d[4 * q + 2]) + bg[u];
                    float zo = __uint_as_float(d[4 * q + 3]) + bo[u];
                    float ig = fast_sigmoid(zi);
                    float fg = fast_sigmoid(zf);
                    float gg = tanh_fast(zg);
                    float og = fast_sigmoid(zo);
                    float cn = fg * cvs[q] + ig * gg;
                    hv[q] = og * tanh_fast(cn);
                    cnv[q] = cn;
                }
                *reinterpret_cast<float4*>(hrow + u0c) =
                    make_float4(hv[0], hv[1], hv[2], hv[3]);
                *reinterpret_cast<float4*>(hrow + u0c + 4) =
                    make_float4(hv[4], hv[5], hv[6], hv[7]);
                *reinterpret_cast<float4*>(corow + u0c) =
                    make_float4(cnv[0], cnv[1], cnv[2], cnv[3]);
                *reinterpret_cast<float4*>(corow + u0c + 4) =
                    make_float4(cnv[4], cnv[5], cnv[6], cnv[7]);
            }
            TCGEN05_WAIT_LD();
            TCGEN05_FENCE_BEFORE();
            MBARRIER_ARRIVE(sb + SM_EPI + 8 * (jj & 1));
        };

        if (wid == 0) {
            int g = 0;
#pragma unroll 1
            for (int j = 0; j < ntiles; j++) {
                // D buffer (j&1) must be free: epilogue of tile j-2 done
                if (j >= 2) {
                    MBARRIER_WAIT_PARITY(sb + SM_EPI + 8 * (j & 1),
                                         ((j >> 1) - 1) & 1);
                }
                uint32_t dD = tmem + (uint32_t)((j & 1) * 256);
#pragma unroll 1
                for (int kt = 0; kt < KTILES; kt++, g++) {
                    MBARRIER_WAIT_PARITY(sb + SM_FULL + 8 * (g % NSTAGES),
                                         (g / NSTAGES) & 1);
                    uint32_t st = sb + SM_STAGE + (g % NSTAGES) * STAGE_BYTES;
                    uint64_t dA = make_desc(st);
                    uint64_t dB = make_desc(st + A_TILE_BYTES);
                    FENCE_PROXY_ASYNC();
                    if (elect_one()) {
#pragma unroll
                        for (int s = 0; s < 4; s++) {   // 4 x K=16 steps
                            mma_f16_ss(dD, dA + s * 2, dB + s * 2,
                                       MMA_IDESC, (kt | s) != 0);
                        }
                        TCGEN05_COMMIT(sb + SM_MMAB + 8 * (g % NSTAGES));
                    }
                }
                // tile j fully committed -> flip tiledone[j&1]
                if (elect_one()) TCGEN05_COMMIT(sb + SM_TDONE + 8 * (j & 1));
                // epilogue of PREVIOUS tile (other D buffer) -- overlaps the
                // tensor pipe chewing tile j's queued MMAs
                if (j >= 1) do_epilogue(j - 1);
            }
            do_epilogue(ntiles - 1);
        } else {
            // warps 1-3: one epilogue per tile, paced by tiledone flips
#pragma unroll 1
            for (int j = 0; j < ntiles; j++) do_epilogue(j);
        }
    }

    __syncthreads();
    if (tid == 0) {
#pragma unroll
        for (int s = 0; s < NSTAGES; s++) {
            MBARRIER_INVAL(sb + SM_FULL + 8 * s);
            MBARRIER_INVAL(sb + SM_MMAB + 8 * s);
        }
        MBARRIER_INVAL(sb + SM_TDONE + 0);
        MBARRIER_INVAL(sb + SM_TDONE + 8);
        MBARRIER_INVAL(sb + SM_EPI + 0);
        MBARRIER_INVAL(sb + SM_EPI + 8);
    }
    __syncthreads();
    if (wid == 0) TCGEN05_DEALLOC(tmem, 512);

#else
    // ======================= SIMT fallback (plain sm_103 target) ===========
    const int PAD = 132;
    float* As = reinterpret_cast<float*>(smem);          // [32][PAD]
    float* Bs = As + 32 * PAD;                           // [32][PAD]

    int tx = tid & 15;
    int ty = tid >> 4;

#pragma unroll 1
    for (int j = 0; j < ntiles; j++) {
        int t = tiles[j];
        int m0 = (t >> 4) * BM;
        int n0 = (t & (NTILES_N - 1)) * BN;

#pragma unroll 1
        for (int ns = 0; ns < 2; ns++) {
            int n0h = n0 + ns * 128;
            int u0 = n0h >> 2;
            float acc[8][8];
#pragma unroll
            for (int i = 0; i < 8; i++)
#pragma unroll
                for (int q = 0; q < 8; q++) acc[i][q] = 0.0f;

#pragma unroll 1
            for (int kt = 0; kt < K_DIM / 32; kt++) {
                int koff = kt * 32;
#pragma unroll
                for (int i = 0; i < 16; i++) {
                    int idx = tid + i * 256;
                    int kk = idx & 31;
                    int r = idx >> 5;
                    size_t ga = (size_t)(m0 + r) * K_DIM + koff + kk;
                    size_t gb = (size_t)(n0h + r) * K_DIM + koff + kk;
                    As[kk * PAD + r] = __half2float(g_A_h[ga]);
                    Bs[kk * PAD + r] = __half2float(g_W_h[gb]);
                }
                __syncthreads();
#pragma unroll 1
                for (int kk = 0; kk < 32; kk++) {
                    float a[8], b[8];
#pragma unroll
                    for (int i = 0; i < 8; i++) a[i] = As[kk * PAD + ty * 8 + i];
#pragma unroll
                    for (int q = 0; q < 8; q++) b[q] = Bs[kk * PAD + tx * 8 + q];
#pragma unroll
                    for (int i = 0; i < 8; i++)
#pragma unroll
                        for (int q = 0; q < 8; q++) acc[i][q] += a[i] * b[q];
                }
                __syncthreads();
            }

#pragma unroll
            for (int i = 0; i < 8; i++) {
                int m = m0 + ty * 8 + i;
#pragma unroll
                for (int jj = 0; jj < 2; jj++) {
                    int u = u0 + tx * 2 + jj;
                    float zi = acc[i][jj * 4 + 0] + bi[u];
                    float zf = acc[i][jj * 4 + 1] + bf_[u];
                    float zg = acc[i][jj * 4 + 2] + bg[u];
                    float zo = acc[i][jj * 4 + 3] + bo[u];
                    float ig = fast_sigmoid(zi);
                    float fg = fast_sigmoid(zf);
                    float gg = tanh_fast(zg);
                    float og = fast_sigmoid(zo);
                    float cv = c_in[(size_t)m * U_DIM + u];
                    float cn = fg * cv + ig * gg;
                    float hn = og * tanh_fast(cn);
                    out[(size_t)m * U_DIM + u] = hn;
                    out[c_off + (size_t)m * U_DIM + u] = cn;
                }
            }
            __syncthreads();
        }
    }
#endif
}

// ---------------- launch ----------------------------------------------------
extern "C" void kernel_launch(void* const* d_in, const int* in_sizes, int n_in,
                              void* d_out, int out_size) {
    const float* x  = (const float*)d_in[0];
    const float* h  = (const float*)d_in[1];
    const float* c  = (const float*)d_in[2];
    const float* Wi = (const float*)d_in[3];
    const float* Wf = (const float*)d_in[4];
    const float* Wg = (const float*)d_in[5];
    const float* Wo = (const float*)d_in[6];
    const float* bi = (const float*)d_in[7];
    const float* bf = (const float*)d_in[8];
    const float* bg = (const float*)d_in[9];
    const float* bo = (const float*)d_in[10];
    float* out = (float*)d_out;

    // 1) fused prep: concat->fp16 A  +  W transpose->fp16
    prep_fused_kernel<<<PREP_A_BLOCKS + PREP_W_BLOCKS, 256>>>(
        x, h, Wi, Wf, Wg, Wo);
    // 2) persistent warp-specialized GEMM + ping-pong overlapped epilogue
    cudaFuncSetAttribute(lstm_gemm_kernel,
                         cudaFuncAttributeMaxDynamicSharedMemorySize, GEMM_SMEM);
    lstm_gemm_kernel<<<GRID_X, GEMM_THREADS, GEMM_SMEM>>>(
        c, bi, bf, bg, bo, out);
}